// round 15
// baseline (speedup 1.0000x reference)
#include <cuda_runtime.h>
#include <cuda_bf16.h>
#include <cstdint>

#define BDIM 8
#define NDIM 2048
#define FIN 16
#define FOUT 64
#define TDIM 12
#define CDIM 192
#define TM 32            // n-tile per CTA
#define MC 32            // m per chunk (= K of one fp8 MMA)
#define NCH (NDIM/MC)    // 64 chunks
#define CT 128           // tensor-path columns (fp8)
#define CF 64            // FFMA-path columns (exact fp32)
#define AST 9            // fp8 A smem word stride
#define XST 9            // fp8 X smem word stride
#define ABUF 288         // words per fp8 A tile (32*9)
#define XBUF 1152        // words per fp8 X tile (128*9)
#define W32OFF (2*ABUF + XBUF)        // 1728: fp32 w tile [2k][32m][32n]
#define X32OFF (W32OFF + 2048)        // 3776: fp32 x tile [32m][64c]
#define BUFW (X32OFF + 2048)          // 5824 words per ping-pong buffer

// ---- device scratch (no cudaMalloc allowed) ----
__device__ float g_deg[NDIM];
__device__ uint32_t g_xTq[(size_t)BDIM*CDIM*(NDIM/4)];  // e4m3 quads: x[b, m..m+3, c] at [b][c][m/4]

// pack 4 floats -> 4 e4m3 bytes (byte0 = a)
__device__ __forceinline__ uint32_t pack4_e4m3(float a, float b, float c, float d) {
    uint16_t lo, hi;
    asm("cvt.rn.satfinite.e4m3x2.f32 %0, %1, %2;" : "=h"(lo) : "f"(b), "f"(a));
    asm("cvt.rn.satfinite.e4m3x2.f32 %0, %1, %2;" : "=h"(hi) : "f"(d), "f"(c));
    return (uint32_t)lo | ((uint32_t)hi << 16);
}
__device__ __forceinline__ unsigned long long dupf2(float v) {
    unsigned long long r;
    uint32_t u = __float_as_uint(v);
    asm("mov.b64 %0, {%1, %1};" : "=l"(r) : "r"(u));
    return r;
}
__device__ __forceinline__ void fma2(unsigned long long& acc, unsigned long long a, unsigned long long b) {
    asm("fma.rn.f32x2 %0, %1, %2, %0;" : "+l"(acc) : "l"(a), "l"(b));
}

// ---------------------------------------------------------------------------
// x[b][m][c] (f32) -> g_xTq[b][c][m/4] (e4m3 x4)
__global__ void xT_kernel(const float* __restrict__ x) {
    __shared__ float t[32][33];
    int b = blockIdx.z, c0 = blockIdx.y * 32, m0 = blockIdx.x * 32;
    int tx = threadIdx.x & 31, ty = threadIdx.x >> 5;
    #pragma unroll
    for (int j = 0; j < 4; j++)
        t[ty + j * 8][tx] = x[((size_t)b * NDIM + m0 + ty + j * 8) * CDIM + c0 + tx];
    __syncthreads();
    int q  = threadIdx.x & 7;
    int cc = threadIdx.x >> 3;
    uint32_t v = pack4_e4m3(t[4 * q][cc], t[4 * q + 1][cc], t[4 * q + 2][cc], t[4 * q + 3][cc]);
    g_xTq[(((size_t)b * CDIM + c0 + cc) << 9) + (m0 >> 2) + q] = v;
}

// ---------------------------------------------------------------------------
// deg[i] = sum_j adj[i][j]  (warp per row)
__global__ void deg_kernel(const float* __restrict__ adj) {
    int row = (blockIdx.x * blockDim.x + threadIdx.x) >> 5;
    int lane = threadIdx.x & 31;
    if (row >= NDIM) return;
    const float4* r = (const float4*)(adj + (size_t)row * NDIM);
    float s = 0.f;
    #pragma unroll
    for (int i = 0; i < 16; i++) {
        float4 v = r[lane + i * 32];
        s += v.x + v.y + v.z + v.w;
    }
    #pragma unroll
    for (int o = 16; o; o >>= 1) s += __shfl_xor_sync(0xffffffffu, s, o);
    if (lane == 0) g_deg[row] = s;
}

// ---------------------------------------------------------------------------
// Hybrid main kernel: cols [0,128) on fp8 m16n8k32 tensor path, cols
// [128,192) on exact fp32 fma.f32x2 path — both pipes of every SMSP busy.
// Ping-pong pipeline, 1 barrier/chunk. Diagonal terms exact in epilogue.
__global__ __launch_bounds__(256, 2)
void main_kernel(const float* __restrict__ x,
                 const float* __restrict__ sa,
                 const float* __restrict__ adj,
                 const float* __restrict__ Theta,
                 float* __restrict__ out)
{
    __shared__ float smem[12288];          // 48 KB: 2 x BUFW = 11648 mainloop; overlay later

    const int b    = blockIdx.y;
    const int n0   = blockIdx.x * TM;
    const int tid  = threadIdx.x;
    const int lane = tid & 31;
    const int wid  = tid >> 5;
    const int g    = lane >> 2;
    const int tig  = lane & 3;
    const int ksel = wid & 1;              // 0 -> k=1, 1 -> k=2 (both paths)
    const int cg0  = (wid >> 1) * 32;      // tensor: 32-col group per warp pair
    const int t128 = (wid >> 1) * 32 + lane;   // 0..127 within ksel-half
    const int fng  = (t128 >> 4) * 4;      // FFMA n base (0..28)
    const int fcg  = (t128 & 15) * 4;      // FFMA c offset (0..60)

    const float* sa0 = sa + (size_t)(b * 3 + 0) * NDIM * NDIM;
    const float* sa1 = sa + (size_t)(b * 3 + 1) * NDIM * NDIM;
    const float* sa2 = sa + (size_t)(b * 3 + 2) * NDIM * NDIM;
    const float* xb  = x + (size_t)b * NDIM * CDIM;
    const uint32_t* xsrc = &g_xTq[((size_t)b * CDIM) << 9];
    const int n_g = n0 + lane;

    float acc[32];                         // tensor acc [2 rt][4 ct][4]
    #pragma unroll
    for (int i = 0; i < 32; i++) acc[i] = 0.f;
    unsigned long long fac[8];             // FFMA acc [4 n][2 cpair] f32x2
    #pragma unroll
    for (int i = 0; i < 8; i++) fac[i] = 0ull;
    float sum0 = 0.f, sum1 = 0.f, sum2 = 0.f;

    // prefetch registers for next chunk
    float ra[4], r0v[4], r1v[4], r2v[4];
    uint32_t nx[4];
    float4 xf[2];

    auto PREFETCH = [&](int ch) {
        int m = ch * MC + wid * 4;
        size_t o0 = (size_t)m * NDIM + n_g;
        #pragma unroll
        for (int i = 0; i < 4; i++) {
            ra[i]  = __ldg(&adj[o0 + (size_t)i * NDIM]);
            r0v[i] = __ldg(&sa0[o0 + (size_t)i * NDIM]);
            r1v[i] = __ldg(&sa1[o0 + (size_t)i * NDIM]);
            r2v[i] = __ldg(&sa2[o0 + (size_t)i * NDIM]);
        }
        #pragma unroll
        for (int i = 0; i < 4; i++) {      // fp8 x: cols 0..127
            int e = tid + i * 256;
            int c = e >> 3, q = e & 7;
            nx[i] = __ldg(&xsrc[((size_t)c << 9) + (ch * MC >> 2) + q]);
        }
        #pragma unroll
        for (int i = 0; i < 2; i++) {      // fp32 x: cols 128..191
            int e = tid + i * 256;         // 0..511 float4 slots
            int mm = e >> 4, f4 = e & 15;
            xf[i] = *(const float4*)&xb[(size_t)(ch * MC + mm) * CDIM + 128 + f4 * 4];
        }
    };

    auto STORE = [&](int ch, int p) {
        float* base = smem + p * BUFW;
        uint32_t* A1w = (uint32_t*)base;
        uint32_t* A2w = (uint32_t*)(base + ABUF);
        uint32_t* Xw  = (uint32_t*)(base + 2 * ABUF);
        float* w32 = base + W32OFF;
        float* x32 = base + X32OFF;
        int mb = ch * MC + wid * 4;
        float w1v[4], w2v[4];
        #pragma unroll
        for (int i = 0; i < 4; i++) {
            float e0 = __expf(r0v[i]);
            float e1 = __expf(r1v[i]);
            float e2 = __expf(r2v[i]);
            sum0 += e0; sum1 += e1; sum2 += e2;
            bool dg = (mb + i == n_g);
            w1v[i] = dg ? 0.f : (-ra[i]) * e1;
            w2v[i] = dg ? 0.f : (2.f * ra[i] * ra[i]) * e2;
            w32[(wid * 4 + i) * 32 + lane]        = w1v[i];
            w32[1024 + (wid * 4 + i) * 32 + lane] = w2v[i];
        }
        A1w[lane * AST + wid] = pack4_e4m3(w1v[0], w1v[1], w1v[2], w1v[3]);
        A2w[lane * AST + wid] = pack4_e4m3(w2v[0], w2v[1], w2v[2], w2v[3]);
        #pragma unroll
        for (int i = 0; i < 4; i++) {
            int e = tid + i * 256;
            int c = e >> 3, q = e & 7;
            Xw[c * XST + q] = nx[i];
        }
        #pragma unroll
        for (int i = 0; i < 2; i++) {
            int e = tid + i * 256;
            int mm = e >> 4, f4 = e & 15;
            *(float4*)&x32[mm * 64 + f4 * 4] = xf[i];
        }
    };

    auto MMA = [&](int p) {
        float* base = smem + p * BUFW;
        const uint32_t* Aw = (const uint32_t*)(base + (ksel ? ABUF : 0));
        const uint32_t* Xw = (const uint32_t*)(base + 2 * ABUF);
        uint32_t afr[2][4];
        #pragma unroll
        for (int rt = 0; rt < 2; rt++) {
            int r0 = rt * 16 + g;
            afr[rt][0] = Aw[r0 * AST + tig];
            afr[rt][1] = Aw[(r0 + 8) * AST + tig];
            afr[rt][2] = Aw[r0 * AST + tig + 4];
            afr[rt][3] = Aw[(r0 + 8) * AST + tig + 4];
        }
        #pragma unroll
        for (int ct = 0; ct < 4; ct++) {
            int c = cg0 + ct * 8 + g;
            uint32_t b0 = Xw[c * XST + tig];
            uint32_t b1 = Xw[c * XST + tig + 4];
            #pragma unroll
            for (int rt = 0; rt < 2; rt++) {
                float* dd = &acc[(rt * 4 + ct) * 4];
                asm volatile(
                    "mma.sync.aligned.m16n8k32.row.col.f32.e4m3.e4m3.f32 "
                    "{%0,%1,%2,%3}, {%4,%5,%6,%7}, {%8,%9}, {%0,%1,%2,%3};\n"
                    : "+f"(dd[0]), "+f"(dd[1]), "+f"(dd[2]), "+f"(dd[3])
                    : "r"(afr[rt][0]), "r"(afr[rt][1]), "r"(afr[rt][2]), "r"(afr[rt][3]),
                      "r"(b0), "r"(b1));
            }
        }
    };

    auto FFMA = [&](int p) {
        float* base = smem + p * BUFW;
        const float* w32 = base + W32OFF + ksel * 1024;
        const float* x32 = base + X32OFF;
        #pragma unroll 8
        for (int m = 0; m < MC; m++) {
            float4 wv = *(const float4*)&w32[m * 32 + fng];
            ulonglong2 xv = *(const ulonglong2*)&x32[m * 64 + fcg];
            unsigned long long w0 = dupf2(wv.x), w1 = dupf2(wv.y);
            unsigned long long w2 = dupf2(wv.z), w3 = dupf2(wv.w);
            fma2(fac[0], w0, xv.x); fma2(fac[1], w0, xv.y);
            fma2(fac[2], w1, xv.x); fma2(fac[3], w1, xv.y);
            fma2(fac[4], w2, xv.x); fma2(fac[5], w2, xv.y);
            fma2(fac[6], w3, xv.x); fma2(fac[7], w3, xv.y);
        }
    };

    // ---- pipelined mainloop: 1 barrier per chunk ----
    PREFETCH(0);
    STORE(0, 0);
    __syncthreads();
    for (int ch = 0; ch < NCH; ch++) {
        int p = ch & 1;
        if (ch + 1 < NCH) PREFETCH(ch + 1);
        MMA(p);
        FFMA(p);
        if (ch + 1 < NCH) STORE(ch + 1, p ^ 1);
        __syncthreads();
    }

    // ---- softmax denominators: reduce 8 partials per column, k=0,1,2 ----
    smem[wid * 32 + lane]       = sum0;
    smem[256 + wid * 32 + lane] = sum1;
    smem[512 + wid * 32 + lane] = sum2;
    __syncthreads();
    if (tid < 96) {
        int k = tid >> 5, nl = tid & 31;
        float s = 0.f;
        #pragma unroll
        for (int w = 0; w < 8; w++) s += smem[k * 256 + w * 32 + nl];
        smem[768 + k * 32 + nl] = 1.f / s;
    }
    __syncthreads();

    const int o    = tid & 63;
    const int ngrp = tid >> 6;
    float inv0r[8], inv1r[8], inv2r[8];
    #pragma unroll
    for (int nn = 0; nn < 8; nn++) {
        int nl = ngrp * 8 + nn;
        inv0r[nn] = smem[768 + nl];
        inv1r[nn] = smem[800 + nl];
        inv2r[nn] = smem[832 + nl];
    }
    __syncthreads();

    // ---- spill accumulators to rhs smem [k][32 n][192 c] ----
    #pragma unroll
    for (int rt = 0; rt < 2; rt++)
        #pragma unroll
        for (int ct = 0; ct < 4; ct++) {
            const float* dd = &acc[(rt * 4 + ct) * 4];
            int r0 = ksel * 32 + rt * 16 + g;
            int c  = cg0 + ct * 8 + 2 * tig;
            *(float2*)&smem[r0 * 192 + c]       = make_float2(dd[0], dd[1]);
            *(float2*)&smem[(r0 + 8) * 192 + c] = make_float2(dd[2], dd[3]);
        }
    #pragma unroll
    for (int i = 0; i < 4; i++) {
        uint32_t l0, h0, l1, h1;
        asm("mov.b64 {%0, %1}, %2;" : "=r"(l0), "=r"(h0) : "l"(fac[i * 2]));
        asm("mov.b64 {%0, %1}, %2;" : "=r"(l1), "=r"(h1) : "l"(fac[i * 2 + 1]));
        float4 v;
        v.x = __uint_as_float(l0); v.y = __uint_as_float(h0);
        v.z = __uint_as_float(l1); v.w = __uint_as_float(h1);
        *(float4*)&smem[(ksel * 32 + fng + i) * 192 + 128 + fcg] = v;
    }
    __syncthreads();

    // ---- epilogue: Theta contraction + exact fp32 diagonal terms + ReLU ----
    float th0[FIN], th1[FIN], th2[FIN];
    #pragma unroll
    for (int f = 0; f < FIN; f++) {
        th0[f] = Theta[f * FOUT + o];
        th1[f] = Theta[(FIN + f) * FOUT + o];
        th2[f] = Theta[(2 * FIN + f) * FOUT + o];
    }

    #pragma unroll 1
    for (int nn = 0; nn < 8; nn++) {
        int nl = ngrp * 8 + nn;
        int n  = n0 + nl;
        float adjd = adj[(size_t)n * NDIM + n];
        float Lnn  = g_deg[n] - adjd;
        float w0 = __expf(sa0[(size_t)n * NDIM + n]) * inv0r[nn];
        float w1 = Lnn * __expf(sa1[(size_t)n * NDIM + n]) * inv1r[nn];
        float w2 = (2.f * Lnn * Lnn - 1.f) * __expf(sa2[(size_t)n * NDIM + n]) * inv2r[nn];

        float vals[TDIM];
        #pragma unroll
        for (int t = 0; t < TDIM; t++) vals[t] = 0.f;
        const float* xr = xb + (size_t)n * CDIM;

        #pragma unroll
        for (int f = 0; f < FIN; f++) {
            float a1f = th1[f] * inv1r[nn];
            float a2f = th2[f] * inv2r[nn];
            float wdf = w0 * th0[f] + w1 * th1[f] + w2 * th2[f];
            #pragma unroll
            for (int tq = 0; tq < 3; tq++) {
                float4 r1 = *(const float4*)&smem[nl * 192 + f * 12 + tq * 4];
                float4 r2 = *(const float4*)&smem[(32 + nl) * 192 + f * 12 + tq * 4];
                float4 xv = *(const float4*)&xr[f * 12 + tq * 4];
                vals[tq * 4 + 0] += r1.x * a1f + r2.x * a2f + xv.x * wdf;
                vals[tq * 4 + 1] += r1.y * a1f + r2.y * a2f + xv.y * wdf;
                vals[tq * 4 + 2] += r1.z * a1f + r2.z * a2f + xv.z * wdf;
                vals[tq * 4 + 3] += r1.w * a1f + r2.w * a2f + xv.w * wdf;
            }
        }
        float* op = out + (((size_t)b * NDIM + n) * FOUT + o) * TDIM;
        #pragma unroll
        for (int tq = 0; tq < 3; tq++) {
            float4 v;
            v.x = fmaxf(vals[tq * 4 + 0], 0.f);
            v.y = fmaxf(vals[tq * 4 + 1], 0.f);
            v.z = fmaxf(vals[tq * 4 + 2], 0.f);
            v.w = fmaxf(vals[tq * 4 + 3], 0.f);
            *(float4*)&op[tq * 4] = v;
        }
    }
}

// ---------------------------------------------------------------------------
extern "C" void kernel_launch(void* const* d_in, const int* in_sizes, int n_in,
                              void* d_out, int out_size) {
    const float* x     = (const float*)d_in[0];  // (B,N,FIN,T)
    const float* sa    = (const float*)d_in[1];  // (B,K,N,N)
    const float* adj   = (const float*)d_in[2];  // (N,N)
    const float* Theta = (const float*)d_in[3];  // (K,FIN,FOUT)
    float* out = (float*)d_out;                  // (B,N,FOUT,T)

    xT_kernel<<<dim3(NDIM / 32, CDIM / 32, BDIM), 256>>>(x);
    deg_kernel<<<NDIM * 32 / 256, 256>>>(adj);
    main_kernel<<<dim3(NDIM / TM, BDIM), 256>>>(x, sa, adj, Theta, out);
}